// round 3
// baseline (speedup 1.0000x reference)
#include <cuda_runtime.h>
#include <math.h>
#include <stdint.h>

typedef unsigned long long u64;

#define NN 3072
#define CA 128
#define CS 384
#define CZ 16
#define NH 4
#define DH 32
#define CF 256
#define LNEPS 1e-5f

#define TQ 32
#define TK 32
#define NSPLIT 8
#define KPS (NN / NSPLIT)
#define NT (KPS / TK)
#define KSTR 132
#define PSTR 36
#define ATHREADS 512

// ---------------- scratch ----------------
static __device__ float g_an[NN*CA];
static __device__ float g_sn[NN*CS];
static __device__ float g_h[NN*CA];
static __device__ float g_q[NN*CA];
static __device__ float g_k[NN*CA];
static __device__ float g_v[NN*CA];
static __device__ float g_g[NN*CA];
static __device__ float g_o[NN*CA];
static __device__ float g_r1[NN*CA];
static __device__ float g_an2[NN*CA];
static __device__ float g_h2[NN*CA];
static __device__ float g_po[(size_t)NSPLIT*NN*CA];
static __device__ float g_pm[NSPLIT*NN*NH];
static __device__ float g_pl[NSPLIT*NN*NH];

__device__ __forceinline__ float sigmoidf_(float x) { return 1.f / (1.f + __expf(-x)); }

// ---------------- packed f32x2 helpers ----------------
__device__ __forceinline__ u64 pk2(float lo, float hi) {
    u64 r; asm("mov.b64 %0, {%1, %2};" : "=l"(r) : "f"(lo), "f"(hi)); return r;
}
__device__ __forceinline__ void upk2(u64 v, float& lo, float& hi) {
    asm("mov.b64 {%0, %1}, %2;" : "=f"(lo), "=f"(hi) : "l"(v));
}
__device__ __forceinline__ u64 f2fma(u64 a, u64 b, u64 c) {
    u64 d; asm("fma.rn.f32x2 %0, %1, %2, %3;" : "=l"(d) : "l"(a), "l"(b), "l"(c)); return d;
}
__device__ __forceinline__ u64 f2add(u64 a, u64 b) {
    u64 d; asm("add.rn.f32x2 %0, %1, %2;" : "=l"(d) : "l"(a), "l"(b)); return d;
}
__device__ __forceinline__ u64 f2mul(u64 a, u64 b) {
    u64 d; asm("mul.rn.f32x2 %0, %1, %2;" : "=l"(d) : "l"(a), "l"(b)); return d;
}
// one LDS.128 -> two packed f32x2
__device__ __forceinline__ void lds2x64(u64& a, u64& b, uint32_t addr) {
    asm volatile("ld.shared.v2.u64 {%0, %1}, [%2];" : "=l"(a), "=l"(b) : "r"(addr));
}

__device__ __forceinline__ void cpa16(void* dst_smem, const void* src) {
    uint32_t d = (uint32_t)__cvta_generic_to_shared(dst_smem);
    asm volatile("cp.async.ca.shared.global [%0], [%1], 16;\n" :: "r"(d), "l"(src));
}
#define CPA_COMMIT() asm volatile("cp.async.commit_group;\n" ::: "memory")
#define CPA_WAIT0()  asm volatile("cp.async.wait_group 0;\n" ::: "memory")

// ---------------- LN (no affine), one row per block ----------------
__device__ __forceinline__ float blockReduceSum128(float v, float* sh) {
    #pragma unroll
    for (int o = 16; o > 0; o >>= 1) v += __shfl_xor_sync(0xffffffffu, v, o);
    __syncthreads();
    if ((threadIdx.x & 31) == 0) sh[threadIdx.x >> 5] = v;
    __syncthreads();
    return sh[0] + sh[1] + sh[2] + sh[3];
}

template <int C>
__global__ void ln_kernel(const float* __restrict__ in, float* __restrict__ out) {
    __shared__ float sh[4];
    constexpr int PT = C / 128;
    int r = blockIdx.x;
    const float* row = in + (size_t)r * C;
    float v[PT];
    float lsum = 0.f;
    #pragma unroll
    for (int i = 0; i < PT; i++) { v[i] = row[threadIdx.x + i * 128]; lsum += v[i]; }
    float mean = blockReduceSum128(lsum, sh) * (1.f / (float)C);
    float lss = 0.f;
    #pragma unroll
    for (int i = 0; i < PT; i++) { float d = v[i] - mean; lss += d * d; }
    float var = blockReduceSum128(lss, sh) * (1.f / (float)C);
    float rs = rsqrtf(var + LNEPS);
    #pragma unroll
    for (int i = 0; i < PT; i++)
        out[(size_t)r * C + threadIdx.x + i * 128] = (v[i] - mean) * rs;
}

// ---------------- AdaLN, 4 rows/block, channel-pair threads ----------------
__global__ void adaln_kernel(const float* __restrict__ an_arr,
                             const float* __restrict__ s_w,
                             const float* __restrict__ scale_w,
                             const float* __restrict__ shift_w,
                             const float* __restrict__ scale_b,
                             float* __restrict__ out) {
    __shared__ float sn_sh[4 * CS];
    int r0 = blockIdx.x * 4;
    int tid = threadIdx.x;
    int cp = tid & 63;       // channel pair: channels 2cp, 2cp+1
    int rg = tid >> 6;       // row group: rows 2rg, 2rg+1
    #pragma unroll
    for (int i = 0; i < 4 * CS / 128; i++) {
        int idx = tid + i * 128;
        sn_sh[idx] = g_sn[(size_t)r0 * CS + idx] * s_w[idx % CS];
    }
    __syncthreads();
    const u64* sw2 = (const u64*)scale_w;
    const u64* hw2 = (const u64*)shift_w;
    u64 a1[2] = {0, 0}, a2[2] = {0, 0};
    #pragma unroll 4
    for (int j = 0; j < CS; j++) {
        u64 w1 = sw2[j * 64 + cp];
        u64 w2 = hw2[j * 64 + cp];
        float sv0 = sn_sh[(2 * rg + 0) * CS + j];
        float sv1 = sn_sh[(2 * rg + 1) * CS + j];
        u64 s0 = pk2(sv0, sv0), s1 = pk2(sv1, sv1);
        a1[0] = f2fma(s0, w1, a1[0]);
        a1[1] = f2fma(s1, w1, a1[1]);
        a2[0] = f2fma(s0, w2, a2[0]);
        a2[1] = f2fma(s1, w2, a2[1]);
    }
    float sb0 = scale_b[2 * cp], sb1 = scale_b[2 * cp + 1];
    #pragma unroll
    for (int rr = 0; rr < 2; rr++) {
        int row = r0 + 2 * rg + rr;
        float x0, x1, y0, y1;
        upk2(a1[rr], x0, x1);
        upk2(a2[rr], y0, y1);
        float2 anv = ((const float2*)an_arr)[(size_t)row * 64 + cp];
        float2 o;
        o.x = sigmoidf_(x0 + sb0) * anv.x + y0;
        o.y = sigmoidf_(x1 + sb1) * anv.y + y1;
        ((float2*)out)[(size_t)row * 64 + cp] = o;
    }
}

// ---------------- QKVG, 4 rows/block, channel-pair threads ----------------
__global__ void qkvg_kernel(const float* __restrict__ wq, const float* __restrict__ bq,
                            const float* __restrict__ wk, const float* __restrict__ wv,
                            const float* __restrict__ wg) {
    __shared__ float h_sh[4 * CA];
    int r0 = blockIdx.x * 4;
    int tid = threadIdx.x;
    int cp = tid & 63;
    int rg = tid >> 6;
    #pragma unroll
    for (int i = 0; i < 4; i++) {
        int idx = tid + i * 128;
        h_sh[idx] = g_h[(size_t)r0 * CA + idx];
    }
    __syncthreads();
    const u64* wA2 = (const u64*)((blockIdx.y == 0) ? wq : wk);
    const u64* wB2 = (const u64*)((blockIdx.y == 0) ? wg : wv);
    u64 aA[2] = {0, 0}, aB[2] = {0, 0};
    #pragma unroll 8
    for (int j = 0; j < CA; j++) {
        u64 w1 = wA2[j * 64 + cp];
        u64 w2 = wB2[j * 64 + cp];
        float h0 = h_sh[(2 * rg + 0) * CA + j];
        float h1 = h_sh[(2 * rg + 1) * CA + j];
        u64 s0 = pk2(h0, h0), s1 = pk2(h1, h1);
        aA[0] = f2fma(s0, w1, aA[0]);
        aA[1] = f2fma(s1, w1, aA[1]);
        aB[0] = f2fma(s0, w2, aB[0]);
        aB[1] = f2fma(s1, w2, aB[1]);
    }
    if (blockIdx.y == 0) {
        const float qscale = 0.17677669529663687f;
        float b0 = bq[2 * cp], b1 = bq[2 * cp + 1];
        #pragma unroll
        for (int rr = 0; rr < 2; rr++) {
            int row = r0 + 2 * rg + rr;
            float x0, x1, y0, y1;
            upk2(aA[rr], x0, x1);
            upk2(aB[rr], y0, y1);
            float2 q; q.x = (x0 + b0) * qscale; q.y = (x1 + b1) * qscale;
            float2 g; g.x = sigmoidf_(y0); g.y = sigmoidf_(y1);
            ((float2*)g_q)[(size_t)row * 64 + cp] = q;
            ((float2*)g_g)[(size_t)row * 64 + cp] = g;
        }
    } else {
        #pragma unroll
        for (int rr = 0; rr < 2; rr++) {
            int row = r0 + 2 * rg + rr;
            float x0, x1, y0, y1;
            upk2(aA[rr], x0, x1);
            upk2(aB[rr], y0, y1);
            float2 k; k.x = x0; k.y = x1;
            float2 v; v.x = y0; v.y = y1;
            ((float2*)g_k)[(size_t)row * 64 + cp] = k;
            ((float2*)g_v)[(size_t)row * 64 + cp] = v;
        }
    }
}

// ---------------- Attention: split-K, cp.async pipelined, f32x2 math ----------------
__global__ void __launch_bounds__(ATHREADS, 1)
attn_kernel(const float* __restrict__ z,
            const float* __restrict__ lnzw,
            const float* __restrict__ lnzb,
            const float* __restrict__ wb) {
    extern __shared__ float sm[];
    float* q_sh = sm;                           // TQ*KSTR
    float* k_sh = q_sh + TQ * KSTR;             // 2*TK*KSTR
    float* v_sh = k_sh + 2 * TK * KSTR;         // 2*TK*KSTR
    float* z_sh = v_sh + 2 * TK * KSTR;         // TQ*TK*16
    float* b_sh = z_sh + TQ * TK * 16;          // TQ*NH*PSTR
    float* p_sh = b_sh + TQ * NH * PSTR;        // TQ*NH*PSTR
    __shared__ __align__(16) float u_sh[NH * CZ];
    __shared__ float su_sh[NH], cbp_sh[NH];

    int tid = threadIdx.x;
    int q0 = blockIdx.x * TQ;
    int kbase = blockIdx.y * KPS;

    // fold LN(z)@wb: u[h][j] = lnzw[j]*wb[j][h]; su[h]=sum u; cbp[h]=sum lnzb[j]*wb[j][h]
    if (tid < 64) {
        int hh = tid >> 4, j = tid & 15;
        u_sh[hh * CZ + j] = lnzw[j] * wb[j * NH + hh];
    } else if (tid < 72) {
        int q = tid - 64;
        int hh = q & 3;
        float acc = 0.f;
        if (q < 4) { for (int j = 0; j < CZ; j++) acc += lnzw[j] * wb[j * NH + hh]; su_sh[hh] = acc; }
        else       { for (int j = 0; j < CZ; j++) acc += lnzb[j] * wb[j * NH + hh]; cbp_sh[hh] = acc; }
    }

    // tile-0 async loads
    {
        int k0 = kbase;
        #pragma unroll
        for (int pi = 0; pi < 2; pi++) {
            int p = tid + pi * 512;
            int qq = p >> 5, kk = p & 31, r = (p >> 1) & 3;
            const float* zp = z + ((size_t)(q0 + qq) * NN + (size_t)(k0 + kk)) * CZ;
            #pragma unroll
            for (int g = 0; g < 4; g++) {
                int slot = (g + r) & 3;
                cpa16(&z_sh[p * 16 + slot * 4], zp + g * 4);
            }
        }
        #pragma unroll
        for (int i = 0; i < 2; i++) {
            int cch = tid + i * 512;
            int row = cch >> 5, c4 = cch & 31;
            cpa16(&k_sh[row * KSTR + c4 * 4], &g_k[(size_t)(k0 + row) * CA + c4 * 4]);
            cpa16(&v_sh[row * KSTR + c4 * 4], &g_v[(size_t)(k0 + row) * CA + c4 * 4]);
        }
    }
    CPA_COMMIT();

    // Q tile
    #pragma unroll
    for (int i = 0; i < 2; i++) {
        int cch = tid + i * 512;
        int row = cch >> 5, c4 = cch & 31;
        *(float4*)&q_sh[row * KSTR + c4 * 4] =
            *(const float4*)&g_q[(size_t)(q0 + row) * CA + c4 * 4];
    }

    int warp = tid >> 5, lane = tid & 31;
    int h = warp & 3;
    int qbase = (warp >> 2) * 8;

    uint32_t z_base = (uint32_t)__cvta_generic_to_shared(z_sh);
    uint32_t u_base = (uint32_t)__cvta_generic_to_shared(u_sh);
    uint32_t q_base = (uint32_t)__cvta_generic_to_shared(q_sh);
    uint32_t k_base = (uint32_t)__cvta_generic_to_shared(k_sh);
    uint32_t p_base = (uint32_t)__cvta_generic_to_shared(p_sh);
    uint32_t qrow[8], prow[8];
    #pragma unroll
    for (int qi = 0; qi < 8; qi++) {
        qrow[qi] = q_base + ((qbase + qi) * KSTR + h * DH) * 4;
        prow[qi] = p_base + ((qbase + qi) * NH + h) * PSTR * 4;
    }

    float m[8], l[8];
    u64 o2[8];
    #pragma unroll
    for (int i = 0; i < 8; i++) { m[i] = -1e30f; l[i] = 0.f; o2[i] = 0ull; }

    for (int t = 0; t < NT; t++) {
        CPA_WAIT0();
        __syncthreads();

        // ---- pair bias (packed dot form) ----
        #pragma unroll
        for (int pi = 0; pi < 2; pi++) {
            int p = tid + pi * 512;
            int qq = p >> 5, kk = p & 31, r = (p >> 1) & 3;
            uint32_t zaddr = z_base + p * 64;
            u64 zp[8];
            #pragma unroll
            for (int g = 0; g < 4; g++) {
                int slot = (g + r) & 3;
                lds2x64(zp[2 * g], zp[2 * g + 1], zaddr + slot * 16);
            }
            u64 s2 = f2add(f2add(zp[0], zp[1]), f2add(zp[2], zp[3]));
            s2 = f2add(s2, f2add(f2add(zp[4], zp[5]), f2add(zp[6], zp[7])));
            u64 zz2 = f2mul(zp[0], zp[0]);
            #pragma unroll
            for (int g = 1; g < 8; g++) zz2 = f2fma(zp[g], zp[g], zz2);
            float bs[NH];
            float slo, shi, zlo, zhi;
            upk2(s2, slo, shi);
            upk2(zz2, zlo, zhi);
            float sum = slo + shi, zz = zlo + zhi;
            float mean = sum * (1.f / 16.f);
            float var = fmaf(-mean, mean, zz * (1.f / 16.f));
            float rs = rsqrtf(var + LNEPS);
            float rm = rs * mean;
            #pragma unroll
            for (int hh = 0; hh < NH; hh++) {
                u64 d2 = 0ull;
                #pragma unroll
                for (int g = 0; g < 4; g++) {
                    u64 cu0, cu1;
                    lds2x64(cu0, cu1, u_base + (hh * CZ + g * 4) * 4);
                    d2 = f2fma(zp[2 * g], cu0, d2);
                    d2 = f2fma(zp[2 * g + 1], cu1, d2);
                }
                float dlo, dhi;
                upk2(d2, dlo, dhi);
                bs[hh] = fmaf(rs, dlo + dhi, fmaf(-rm, su_sh[hh], cbp_sh[hh]));
            }
            #pragma unroll
            for (int hh = 0; hh < NH; hh++)
                b_sh[(qq * NH + hh) * PSTR + kk] = bs[hh];
        }
        __syncthreads();

        // ---- prefetch tile t+1 ----
        if (t + 1 < NT) {
            int k0 = kbase + (t + 1) * TK;
            int buf = (t + 1) & 1;
            #pragma unroll
            for (int pi = 0; pi < 2; pi++) {
                int p = tid + pi * 512;
                int qq = p >> 5, kk = p & 31, r = (p >> 1) & 3;
                const float* zp = z + ((size_t)(q0 + qq) * NN + (size_t)(k0 + kk)) * CZ;
                #pragma unroll
                for (int g = 0; g < 4; g++) {
                    int slot = (g + r) & 3;
                    cpa16(&z_sh[p * 16 + slot * 4], zp + g * 4);
                }
            }
            #pragma unroll
            for (int i = 0; i < 2; i++) {
                int cch = tid + i * 512;
                int row = cch >> 5, c4 = cch & 31;
                cpa16(&k_sh[buf * TK * KSTR + row * KSTR + c4 * 4],
                      &g_k[(size_t)(k0 + row) * CA + c4 * 4]);
                cpa16(&v_sh[buf * TK * KSTR + row * KSTR + c4 * 4],
                      &g_v[(size_t)(k0 + row) * CA + c4 * 4]);
            }
        }
        CPA_COMMIT();

        uint32_t kaddr = k_base + ((t & 1) * TK * KSTR + lane * KSTR + h * DH) * 4;
        const float* vbuf = v_sh + (t & 1) * TK * KSTR;

        // ---- logits (packed over d) ----
        u64 lg2[8];
        #pragma unroll
        for (int qi = 0; qi < 8; qi++) lg2[qi] = 0ull;
        #pragma unroll
        for (int d4 = 0; d4 < 8; d4++) {
            u64 k0p, k1p;
            lds2x64(k0p, k1p, kaddr + d4 * 16);
            #pragma unroll
            for (int qi = 0; qi < 8; qi++) {
                u64 q0p, q1p;
                lds2x64(q0p, q1p, qrow[qi] + d4 * 16);
                lg2[qi] = f2fma(q0p, k0p, lg2[qi]);
                lg2[qi] = f2fma(q1p, k1p, lg2[qi]);
            }
        }
        // ---- online softmax ----
        float scl[8];
        #pragma unroll
        for (int qi = 0; qi < 8; qi++) {
            float llo, lhi;
            upk2(lg2[qi], llo, lhi);
            float lg = llo + lhi + b_sh[((qbase + qi) * NH + h) * PSTR + lane];
            float mx = lg;
            #pragma unroll
            for (int o = 16; o > 0; o >>= 1)
                mx = fmaxf(mx, __shfl_xor_sync(0xffffffffu, mx, o));
            float mn = fmaxf(m[qi], mx);
            float p = __expf(lg - mn);
            float sum = p;
            #pragma unroll
            for (int o = 16; o > 0; o >>= 1)
                sum += __shfl_xor_sync(0xffffffffu, sum, o);
            float sc = __expf(m[qi] - mn);
            l[qi] = l[qi] * sc + sum;
            m[qi] = mn;
            scl[qi] = sc;
            p_sh[((qbase + qi) * NH + h) * PSTR + lane] = p;
        }
        __syncwarp();
        // ---- PV (packed over k) ----
        #pragma unroll
        for (int qi = 0; qi < 8; qi++) o2[qi] = f2mul(o2[qi], pk2(scl[qi], scl[qi]));
        #pragma unroll
        for (int k4 = 0; k4 < 8; k4++) {
            float va0 = vbuf[(k4 * 4 + 0) * KSTR + h * DH + lane];
            float va1 = vbuf[(k4 * 4 + 1) * KSTR + h * DH + lane];
            float va2 = vbuf[(k4 * 4 + 2) * KSTR + h * DH + lane];
            float va3 = vbuf[(k4 * 4 + 3) * KSTR + h * DH + lane];
            u64 v01 = pk2(va0, va1), v23 = pk2(va2, va3);
            #pragma unroll
            for (int qi = 0; qi < 8; qi++) {
                u64 p01, p23;
                lds2x64(p01, p23, prow[qi] + k4 * 16);
                o2[qi] = f2fma(p01, v01, o2[qi]);
                o2[qi] = f2fma(p23, v23, o2[qi]);
            }
        }
    }
    // write partials
    size_t sp = blockIdx.y;
    #pragma unroll
    for (int qi = 0; qi < 8; qi++) {
        int q = q0 + qbase + qi;
        float olo, ohi;
        upk2(o2[qi], olo, ohi);
        g_po[(sp * NN + q) * CA + h * DH + lane] = olo + ohi;
        if (lane == 0) {
            g_pm[(sp * NN + q) * NH + h] = m[qi];
            g_pl[(sp * NN + q) * NH + h] = l[qi];
        }
    }
}

// ---------------- split-K combine ----------------
__global__ void combine_kernel() {
    int tid = threadIdx.x;               // 256
    int q = blockIdx.x * 2 + (tid >> 7);
    int hd = tid & 127;
    int h = hd >> 5;
    float ms[NSPLIT];
    float M = -1e30f;
    #pragma unroll
    for (int s = 0; s < NSPLIT; s++) {
        ms[s] = g_pm[((size_t)s * NN + q) * NH + h];
        M = fmaxf(M, ms[s]);
    }
    float osum = 0.f, lsum = 0.f;
    #pragma unroll
    for (int s = 0; s < NSPLIT; s++) {
        float w = __expf(ms[s] - M);
        lsum = fmaf(w, g_pl[((size_t)s * NN + q) * NH + h], lsum);
        osum = fmaf(w, g_po[((size_t)s * NN + q) * CA + hd], osum);
    }
    g_o[(size_t)q * CA + hd] = osum / lsum;
}

// ---------------- output proj + style gate + residual 1 ----------------
__global__ void attnout_kernel(const float* __restrict__ wo,
                               const float* __restrict__ s,
                               const float* __restrict__ sg1w,
                               const float* __restrict__ sg1b,
                               const float* __restrict__ a) {
    __shared__ float go_sh[4 * CA];
    __shared__ float s_sh[4 * CS];
    int r0 = blockIdx.x * 4;
    int tid = threadIdx.x;
    int cp = tid & 63;
    int rg = tid >> 6;
    #pragma unroll
    for (int i = 0; i < 4; i++) {
        int idx = tid + i * 128;
        go_sh[idx] = g_g[(size_t)r0 * CA + idx] * g_o[(size_t)r0 * CA + idx];
    }
    #pragma unroll
    for (int i = 0; i < 4 * CS / 128; i++) {
        int idx = tid + i * 128;
        s_sh[idx] = s[(size_t)r0 * CS + idx];
    }
    __syncthreads();
    const u64* wo2 = (const u64*)wo;
    const u64* sg2 = (const u64*)sg1w;
    u64 aA[2] = {0, 0};
    #pragma unroll 8
    for (int j = 0; j < CA; j++) {
        u64 w = wo2[j * 64 + cp];
        float g0 = go_sh[(2 * rg + 0) * CA + j];
        float g1 = go_sh[(2 * rg + 1) * CA + j];
        aA[0] = f2fma(pk2(g0, g0), w, aA[0]);
        aA[1] = f2fma(pk2(g1, g1), w, aA[1]);
    }
    u64 aG[2] = {0, 0};
    #pragma unroll 4
    for (int j = 0; j < CS; j++) {
        u64 w = sg2[j * 64 + cp];
        float s0 = s_sh[(2 * rg + 0) * CS + j];
        float s1 = s_sh[(2 * rg + 1) * CS + j];
        aG[0] = f2fma(pk2(s0, s0), w, aG[0]);
        aG[1] = f2fma(pk2(s1, s1), w, aG[1]);
    }
    float gb0 = sg1b[2 * cp], gb1 = sg1b[2 * cp + 1];
    #pragma unroll
    for (int rr = 0; rr < 2; rr++) {
        int row = r0 + 2 * rg + rr;
        float x0, x1, y0, y1;
        upk2(aA[rr], x0, x1);
        upk2(aG[rr], y0, y1);
        float2 av = ((const float2*)a)[(size_t)row * 64 + cp];
        float2 o;
        o.x = sigmoidf_(y0 + gb0) * x0 + av.x;
        o.y = sigmoidf_(y1 + gb1) * x1 + av.y;
        ((float2*)g_r1)[(size_t)row * 64 + cp] = o;
    }
}

// ---------------- SwiGLU FFN + gate + residual 2, 256 threads, 4 rows ----------------
__global__ void ffn_kernel(const float* __restrict__ w1, const float* __restrict__ w2,
                           const float* __restrict__ wout,
                           const float* __restrict__ s,
                           const float* __restrict__ sg2w, const float* __restrict__ sg2b,
                           float* __restrict__ out) {
    __shared__ float h_sh[4 * CA];
    __shared__ float s_sh[4 * CS];
    __shared__ __align__(16) float gt_sh[4 * CF];
    int r0 = blockIdx.x * 4;
    int tid = threadIdx.x;   // 256
    for (int i = tid; i < 4 * CA; i += 256) h_sh[i] = g_h2[(size_t)r0 * CA + i];
    for (int i = tid; i < 4 * CS; i += 256) s_sh[i] = s[(size_t)r0 * CS + i];
    __syncthreads();
    {
        int cp = tid & 127;     // channel pair of CF
        int rg = tid >> 7;      // rows 2rg, 2rg+1
        const u64* w1p = (const u64*)w1;
        const u64* w2p = (const u64*)w2;
        u64 u1[2] = {0, 0}, u2[2] = {0, 0};
        #pragma unroll 8
        for (int j = 0; j < CA; j++) {
            u64 wa = w1p[j * 128 + cp];
            u64 wb2 = w2p[j * 128 + cp];
            float h0 = h_sh[(2 * rg + 0) * CA + j];
            float h1 = h_sh[(2 * rg + 1) * CA + j];
            u64 s0 = pk2(h0, h0), s1 = pk2(h1, h1);
            u1[0] = f2fma(s0, wa, u1[0]);
            u1[1] = f2fma(s1, wa, u1[1]);
            u2[0] = f2fma(s0, wb2, u2[0]);
            u2[1] = f2fma(s1, wb2, u2[1]);
        }
        #pragma unroll
        for (int rr = 0; rr < 2; rr++) {
            float x0, x1, y0, y1;
            upk2(u1[rr], x0, x1);
            upk2(u2[rr], y0, y1);
            float g0 = (x0 * sigmoidf_(x0)) * y0;
            float g1 = (x1 * sigmoidf_(x1)) * y1;
            ((u64*)gt_sh)[(2 * rg + rr) * 128 + cp] = pk2(g0, g1);
        }
    }
    __syncthreads();
    {
        int cp = tid & 63;      // channel pair of CA
        int rw = tid >> 6;      // one row each
        const u64* wop = (const u64*)wout;
        const u64* sgp = (const u64*)sg2w;
        u64 aF = 0, aG = 0;
        #pragma unroll 8
        for (int j = 0; j < CF; j++) {
            u64 w = wop[j * 64 + cp];
            float gv = gt_sh[rw * CF + j];
            aF = f2fma(pk2(gv, gv), w, aF);
        }
        #pragma unroll 4
        for (int j = 0; j < CS; j++) {
            u64 w = sgp[j * 64 + cp];
            float sv = s_sh[rw * CS + j];
            aG = f2fma(pk2(sv, sv), w, aG);
        }
        float f0, f1, g0, g1;
        upk2(aF, f0, f1);
        upk2(aG, g0, g1);
        int row = r0 + rw;
        float2 rv = ((const float2*)g_r1)[(size_t)row * 64 + cp];
        float2 o;
        o.x = sigmoidf_(g0 + sg2b[2 * cp]) * f0 + rv.x;
        o.y = sigmoidf_(g1 + sg2b[2 * cp + 1]) * f1 + rv.y;
        ((float2*)out)[(size_t)row * 64 + cp] = o;
    }
}

// ---------------- launch ----------------
extern "C" void kernel_launch(void* const* d_in, const int* in_sizes, int n_in,
                              void* d_out, int out_size) {
    const float* a      = (const float*)d_in[0];
    const float* s      = (const float*)d_in[1];
    const float* z      = (const float*)d_in[2];
    const float* a1sw   = (const float*)d_in[3];
    const float* a1scw  = (const float*)d_in[4];
    const float* a1scb  = (const float*)d_in[5];
    const float* a1shw  = (const float*)d_in[6];
    const float* wq     = (const float*)d_in[7];
    const float* bq     = (const float*)d_in[8];
    const float* wk     = (const float*)d_in[9];
    const float* wv     = (const float*)d_in[10];
    const float* lnzw   = (const float*)d_in[11];
    const float* lnzb   = (const float*)d_in[12];
    const float* wb     = (const float*)d_in[13];
    const float* wg     = (const float*)d_in[14];
    const float* wo     = (const float*)d_in[15];
    const float* sg1w   = (const float*)d_in[16];
    const float* sg1b   = (const float*)d_in[17];
    const float* a2sw   = (const float*)d_in[18];
    const float* a2scw  = (const float*)d_in[19];
    const float* a2scb  = (const float*)d_in[20];
    const float* a2shw  = (const float*)d_in[21];
    const float* w1     = (const float*)d_in[22];
    const float* w2     = (const float*)d_in[23];
    const float* wout   = (const float*)d_in[24];
    const float* sg2w   = (const float*)d_in[25];
    const float* sg2b   = (const float*)d_in[26];
    float* out = (float*)d_out;

    const int ATTN_SMEM =
        (TQ * KSTR + 4 * TK * KSTR + TQ * TK * 16 + 2 * TQ * NH * PSTR) * 4;
    static int attrset = 0;
    if (!attrset) {
        cudaFuncSetAttribute(attn_kernel, cudaFuncAttributeMaxDynamicSharedMemorySize, ATTN_SMEM);
        attrset = 1;
    }

    ln_kernel<CA><<<NN, 128>>>(a, g_an);
    ln_kernel<CS><<<NN, 128>>>(s, g_sn);
    adaln_kernel<<<NN / 4, 128>>>(g_an, a1sw, a1scw, a1shw, a1scb, g_h);
    qkvg_kernel<<<dim3(NN / 4, 2), 128>>>(wq, bq, wk, wv, wg);
    attn_kernel<<<dim3(NN / TQ, NSPLIT), ATHREADS, ATTN_SMEM>>>(z, lnzw, lnzb, wb);
    combine_kernel<<<NN / 2, 256>>>();
    attnout_kernel<<<NN / 4, 128>>>(wo, s, sg1w, sg1b, a);
    ln_kernel<CA><<<NN, 128>>>(g_r1, g_an2);
    adaln_kernel<<<NN / 4, 128>>>(g_an2, a2sw, a2scw, a2shw, a2scb, g_h2);
    ffn_kernel<<<NN / 4, 256>>>(w1, w2, wout, s, sg2w, sg2b, out);
    (void)in_sizes; (void)n_in; (void)out_size;
}

// round 4
// speedup vs baseline: 1.1745x; 1.1745x over previous
#include <cuda_runtime.h>
#include <math.h>
#include <stdint.h>

typedef unsigned long long u64;

#define NN 3072
#define CA 128
#define CS 384
#define CZ 16
#define NH 4
#define DH 32
#define CF 256
#define LNEPS 1e-5f

#define TQ 32
#define TK 32
#define NSPLIT 8
#define KPS (NN / NSPLIT)
#define NT (KPS / TK)
#define KSTR 132
#define PSTR 36
#define ATHREADS 256

// ---------------- scratch ----------------
static __device__ float g_an[NN*CA];
static __device__ float g_sn[NN*CS];
static __device__ float g_h[NN*CA];
static __device__ float g_q[NN*CA];
static __device__ float g_k[NN*CA];
static __device__ float g_v[NN*CA];
static __device__ float g_g[NN*CA];
static __device__ float g_o[NN*CA];
static __device__ float g_r1[NN*CA];
static __device__ float g_an2[NN*CA];
static __device__ float g_h2[NN*CA];
static __device__ float g_po[(size_t)NSPLIT*NN*CA];
static __device__ float g_pm[NSPLIT*NN*NH];
static __device__ float g_pl[NSPLIT*NN*NH];

__device__ __forceinline__ float sigmoidf_(float x) { return 1.f / (1.f + __expf(-x)); }

// ---------------- packed f32x2 helpers ----------------
__device__ __forceinline__ u64 pk2(float lo, float hi) {
    u64 r; asm("mov.b64 %0, {%1, %2};" : "=l"(r) : "f"(lo), "f"(hi)); return r;
}
__device__ __forceinline__ void upk2(u64 v, float& lo, float& hi) {
    asm("mov.b64 {%0, %1}, %2;" : "=f"(lo), "=f"(hi) : "l"(v));
}
__device__ __forceinline__ u64 f2fma(u64 a, u64 b, u64 c) {
    u64 d; asm("fma.rn.f32x2 %0, %1, %2, %3;" : "=l"(d) : "l"(a), "l"(b), "l"(c)); return d;
}
__device__ __forceinline__ u64 f2add(u64 a, u64 b) {
    u64 d; asm("add.rn.f32x2 %0, %1, %2;" : "=l"(d) : "l"(a), "l"(b)); return d;
}
__device__ __forceinline__ u64 f2mul(u64 a, u64 b) {
    u64 d; asm("mul.rn.f32x2 %0, %1, %2;" : "=l"(d) : "l"(a), "l"(b)); return d;
}
__device__ __forceinline__ void lds2x64(u64& a, u64& b, uint32_t addr) {
    asm volatile("ld.shared.v2.u64 {%0, %1}, [%2];" : "=l"(a), "=l"(b) : "r"(addr));
}

// ---------------- tf32 mma helpers ----------------
__device__ __forceinline__ uint32_t tf32c(float x) {
    uint32_t r; asm("cvt.rna.tf32.f32 %0, %1;" : "=r"(r) : "f"(x)); return r;
}
__device__ __forceinline__ void mma16n8k8(float* c, const uint32_t* a, uint32_t b0, uint32_t b1) {
    asm volatile(
        "mma.sync.aligned.m16n8k8.row.col.f32.tf32.tf32.f32 "
        "{%0,%1,%2,%3}, {%4,%5,%6,%7}, {%8,%9}, {%0,%1,%2,%3};"
        : "+f"(c[0]), "+f"(c[1]), "+f"(c[2]), "+f"(c[3])
        : "r"(a[0]), "r"(a[1]), "r"(a[2]), "r"(a[3]), "r"(b0), "r"(b1));
}

__device__ __forceinline__ void cpa16(void* dst_smem, const void* src) {
    uint32_t d = (uint32_t)__cvta_generic_to_shared(dst_smem);
    asm volatile("cp.async.ca.shared.global [%0], [%1], 16;\n" :: "r"(d), "l"(src));
}
#define CPA_COMMIT() asm volatile("cp.async.commit_group;\n" ::: "memory")
#define CPA_WAIT0()  asm volatile("cp.async.wait_group 0;\n" ::: "memory")

// ---------------- LN (no affine) ----------------
__device__ __forceinline__ float blockReduceSum128(float v, float* sh) {
    #pragma unroll
    for (int o = 16; o > 0; o >>= 1) v += __shfl_xor_sync(0xffffffffu, v, o);
    __syncthreads();
    if ((threadIdx.x & 31) == 0) sh[threadIdx.x >> 5] = v;
    __syncthreads();
    return sh[0] + sh[1] + sh[2] + sh[3];
}

template <int C>
__global__ void ln_kernel(const float* __restrict__ in, float* __restrict__ out) {
    __shared__ float sh[4];
    constexpr int PT = C / 128;
    int r = blockIdx.x;
    const float* row = in + (size_t)r * C;
    float v[PT];
    float lsum = 0.f;
    #pragma unroll
    for (int i = 0; i < PT; i++) { v[i] = row[threadIdx.x + i * 128]; lsum += v[i]; }
    float mean = blockReduceSum128(lsum, sh) * (1.f / (float)C);
    float lss = 0.f;
    #pragma unroll
    for (int i = 0; i < PT; i++) { float d = v[i] - mean; lss += d * d; }
    float var = blockReduceSum128(lss, sh) * (1.f / (float)C);
    float rs = rsqrtf(var + LNEPS);
    #pragma unroll
    for (int i = 0; i < PT; i++)
        out[(size_t)r * C + threadIdx.x + i * 128] = (v[i] - mean) * rs;
}

// ---------------- AdaLN, 16 rows/block, 512 threads ----------------
__global__ void adaln_kernel(const float* __restrict__ an_arr,
                             const float* __restrict__ s_w,
                             const float* __restrict__ scale_w,
                             const float* __restrict__ shift_w,
                             const float* __restrict__ scale_b,
                             float* __restrict__ out) {
    __shared__ float sn_sh[16 * CS];
    int r0 = blockIdx.x * 16;
    int tid = threadIdx.x;
    int cp = tid & 63;       // channel pair
    int rg = tid >> 6;       // 0..7 -> rows 2rg, 2rg+1
    for (int i = tid; i < 16 * CS; i += 512)
        sn_sh[i] = g_sn[(size_t)r0 * CS + i] * s_w[i % CS];
    __syncthreads();
    const u64* sw2 = (const u64*)scale_w;
    const u64* hw2 = (const u64*)shift_w;
    u64 a1[2] = {0, 0}, a2[2] = {0, 0};
    #pragma unroll 4
    for (int j = 0; j < CS; j++) {
        u64 w1 = sw2[j * 64 + cp];
        u64 w2 = hw2[j * 64 + cp];
        float sv0 = sn_sh[(2 * rg + 0) * CS + j];
        float sv1 = sn_sh[(2 * rg + 1) * CS + j];
        u64 s0 = pk2(sv0, sv0), s1 = pk2(sv1, sv1);
        a1[0] = f2fma(s0, w1, a1[0]);
        a1[1] = f2fma(s1, w1, a1[1]);
        a2[0] = f2fma(s0, w2, a2[0]);
        a2[1] = f2fma(s1, w2, a2[1]);
    }
    float sb0 = scale_b[2 * cp], sb1 = scale_b[2 * cp + 1];
    #pragma unroll
    for (int rr = 0; rr < 2; rr++) {
        int row = r0 + 2 * rg + rr;
        float x0, x1, y0, y1;
        upk2(a1[rr], x0, x1);
        upk2(a2[rr], y0, y1);
        float2 anv = ((const float2*)an_arr)[(size_t)row * 64 + cp];
        float2 o;
        o.x = sigmoidf_(x0 + sb0) * anv.x + y0;
        o.y = sigmoidf_(x1 + sb1) * anv.y + y1;
        ((float2*)out)[(size_t)row * 64 + cp] = o;
    }
}

// ---------------- QKVG, 16 rows/block, 512 threads ----------------
__global__ void qkvg_kernel(const float* __restrict__ wq, const float* __restrict__ bq,
                            const float* __restrict__ wk, const float* __restrict__ wv,
                            const float* __restrict__ wg) {
    __shared__ float h_sh[16 * CA];
    int r0 = blockIdx.x * 16;
    int tid = threadIdx.x;
    int cp = tid & 63;
    int rg = tid >> 6;   // 0..7
    for (int i = tid; i < 16 * CA; i += 512)
        h_sh[i] = g_h[(size_t)r0 * CA + i];
    __syncthreads();
    const u64* wA2 = (const u64*)((blockIdx.y == 0) ? wq : wk);
    const u64* wB2 = (const u64*)((blockIdx.y == 0) ? wg : wv);
    u64 aA[2] = {0, 0}, aB[2] = {0, 0};
    #pragma unroll 8
    for (int j = 0; j < CA; j++) {
        u64 w1 = wA2[j * 64 + cp];
        u64 w2 = wB2[j * 64 + cp];
        float h0 = h_sh[(2 * rg + 0) * CA + j];
        float h1 = h_sh[(2 * rg + 1) * CA + j];
        u64 s0 = pk2(h0, h0), s1 = pk2(h1, h1);
        aA[0] = f2fma(s0, w1, aA[0]);
        aA[1] = f2fma(s1, w1, aA[1]);
        aB[0] = f2fma(s0, w2, aB[0]);
        aB[1] = f2fma(s1, w2, aB[1]);
    }
    if (blockIdx.y == 0) {
        const float qscale = 0.17677669529663687f;
        float b0 = bq[2 * cp], b1 = bq[2 * cp + 1];
        #pragma unroll
        for (int rr = 0; rr < 2; rr++) {
            int row = r0 + 2 * rg + rr;
            float x0, x1, y0, y1;
            upk2(aA[rr], x0, x1);
            upk2(aB[rr], y0, y1);
            float2 q; q.x = (x0 + b0) * qscale; q.y = (x1 + b1) * qscale;
            float2 g; g.x = sigmoidf_(y0); g.y = sigmoidf_(y1);
            ((float2*)g_q)[(size_t)row * 64 + cp] = q;
            ((float2*)g_g)[(size_t)row * 64 + cp] = g;
        }
    } else {
        #pragma unroll
        for (int rr = 0; rr < 2; rr++) {
            int row = r0 + 2 * rg + rr;
            float x0, x1, y0, y1;
            upk2(aA[rr], x0, x1);
            upk2(aB[rr], y0, y1);
            ((float2*)g_k)[(size_t)row * 64 + cp] = make_float2(x0, x1);
            ((float2*)g_v)[(size_t)row * 64 + cp] = make_float2(y0, y1);
        }
    }
}

// ---------------- Attention: split-K, cp.async pipelined, tf32 mma ----------------
// 256 threads = 8 warps; warp = (head, q-half of 16 rows)
__global__ void __launch_bounds__(ATHREADS, 1)
attn_kernel(const float* __restrict__ z,
            const float* __restrict__ lnzw,
            const float* __restrict__ lnzb,
            const float* __restrict__ wb) {
    extern __shared__ float sm[];
    float* q_sh = sm;                           // TQ*KSTR
    float* k_sh = q_sh + TQ * KSTR;             // 2*TK*KSTR
    float* v_sh = k_sh + 2 * TK * KSTR;         // 2*TK*KSTR
    float* z_sh = v_sh + 2 * TK * KSTR;         // TQ*TK*16
    float* b_sh = z_sh + TQ * TK * 16;          // TQ*NH*PSTR
    float* p_sh = b_sh + TQ * NH * PSTR;        // 8 warps * 16 * PSTR
    __shared__ __align__(16) float u_sh[NH * CZ];
    __shared__ float su_sh[NH], cbp_sh[NH];

    int tid = threadIdx.x;
    int q0 = blockIdx.x * TQ;
    int kbase = blockIdx.y * KPS;

    if (tid < 64) {
        int hh = tid >> 4, j = tid & 15;
        u_sh[hh * CZ + j] = lnzw[j] * wb[j * NH + hh];
    } else if (tid < 72) {
        int q = tid - 64;
        int hh = q & 3;
        float acc = 0.f;
        if (q < 4) { for (int j = 0; j < CZ; j++) acc += lnzw[j] * wb[j * NH + hh]; su_sh[hh] = acc; }
        else       { for (int j = 0; j < CZ; j++) acc += lnzb[j] * wb[j * NH + hh]; cbp_sh[hh] = acc; }
    }

    // tile-0 async loads
    {
        int k0 = kbase;
        #pragma unroll
        for (int pi = 0; pi < 4; pi++) {
            int p = tid + pi * 256;
            int qq = p >> 5, kk = p & 31, r = (p >> 1) & 3;
            const float* zp = z + ((size_t)(q0 + qq) * NN + (size_t)(k0 + kk)) * CZ;
            #pragma unroll
            for (int g = 0; g < 4; g++) {
                int slot = (g + r) & 3;
                cpa16(&z_sh[p * 16 + slot * 4], zp + g * 4);
            }
        }
        #pragma unroll
        for (int i = 0; i < 4; i++) {
            int cch = tid + i * 256;
            int row = cch >> 5, c4 = cch & 31;
            cpa16(&k_sh[row * KSTR + c4 * 4], &g_k[(size_t)(k0 + row) * CA + c4 * 4]);
            cpa16(&v_sh[row * KSTR + c4 * 4], &g_v[(size_t)(k0 + row) * CA + c4 * 4]);
        }
    }
    CPA_COMMIT();

    // Q tile (regular loads)
    #pragma unroll
    for (int i = 0; i < 4; i++) {
        int cch = tid + i * 256;
        int row = cch >> 5, c4 = cch & 31;
        *(float4*)&q_sh[row * KSTR + c4 * 4] =
            *(const float4*)&g_q[(size_t)(q0 + row) * CA + c4 * 4];
    }
    __syncthreads();

    int warp = tid >> 5, lane = tid & 31;
    int h = warp & 3;
    int qg = warp >> 2;          // 0 or 1: q rows qg*16 .. qg*16+15
    int g = lane >> 2;           // fragment row group 0..7
    int t4 = lane & 3;
    int rowg = qg * 16 + g;      // this thread's first q row; second is rowg+8

    // Q fragments (tile-invariant): a[dc][0..3]
    uint32_t qa[16];
    #pragma unroll
    for (int dc = 0; dc < 4; dc++) {
        const float* qp = &q_sh[rowg * KSTR + h * DH + dc * 8 + t4];
        qa[dc * 4 + 0] = tf32c(qp[0]);
        qa[dc * 4 + 1] = tf32c(qp[8 * KSTR]);
        qa[dc * 4 + 2] = tf32c(qp[4]);
        qa[dc * 4 + 3] = tf32c(qp[8 * KSTR + 4]);
    }

    float* pw = p_sh + warp * 16 * PSTR;

    float m0 = -1e30f, m1 = -1e30f, l0 = 0.f, l1 = 0.f;
    float o[4][4];
    #pragma unroll
    for (int nb = 0; nb < 4; nb++)
        #pragma unroll
        for (int i = 0; i < 4; i++) o[nb][i] = 0.f;

    uint32_t z_base = (uint32_t)__cvta_generic_to_shared(z_sh);
    uint32_t u_base = (uint32_t)__cvta_generic_to_shared(u_sh);

    for (int t = 0; t < NT; t++) {
        CPA_WAIT0();
        __syncthreads();

        // ---- pair bias (4 pairs per thread) ----
        #pragma unroll
        for (int pi = 0; pi < 4; pi++) {
            int p = tid + pi * 256;
            int qq = p >> 5, kk = p & 31, r = (p >> 1) & 3;
            uint32_t zaddr = z_base + p * 64;
            u64 zp[8];
            #pragma unroll
            for (int gg = 0; gg < 4; gg++) {
                int slot = (gg + r) & 3;
                lds2x64(zp[2 * gg], zp[2 * gg + 1], zaddr + slot * 16);
            }
            u64 s2 = f2add(f2add(zp[0], zp[1]), f2add(zp[2], zp[3]));
            s2 = f2add(s2, f2add(f2add(zp[4], zp[5]), f2add(zp[6], zp[7])));
            u64 zz2 = f2mul(zp[0], zp[0]);
            #pragma unroll
            for (int gg = 1; gg < 8; gg++) zz2 = f2fma(zp[gg], zp[gg], zz2);
            float slo, shi, zlo, zhi;
            upk2(s2, slo, shi);
            upk2(zz2, zlo, zhi);
            float sum = slo + shi, zz = zlo + zhi;
            float mean = sum * (1.f / 16.f);
            float var = fmaf(-mean, mean, zz * (1.f / 16.f));
            float rs = rsqrtf(var + LNEPS);
            float rm = rs * mean;
            float bs[NH];
            #pragma unroll
            for (int hh = 0; hh < NH; hh++) {
                u64 d2 = 0ull;
                #pragma unroll
                for (int gg = 0; gg < 4; gg++) {
                    u64 cu0, cu1;
                    lds2x64(cu0, cu1, u_base + (hh * CZ + gg * 4) * 4);
                    d2 = f2fma(zp[2 * gg], cu0, d2);
                    d2 = f2fma(zp[2 * gg + 1], cu1, d2);
                }
                float dlo, dhi;
                upk2(d2, dlo, dhi);
                bs[hh] = fmaf(rs, dlo + dhi, fmaf(-rm, su_sh[hh], cbp_sh[hh]));
            }
            #pragma unroll
            for (int hh = 0; hh < NH; hh++)
                b_sh[(qq * NH + hh) * PSTR + kk] = bs[hh];
        }
        __syncthreads();

        // ---- prefetch tile t+1 ----
        if (t + 1 < NT) {
            int k0 = kbase + (t + 1) * TK;
            int buf = (t + 1) & 1;
            #pragma unroll
            for (int pi = 0; pi < 4; pi++) {
                int p = tid + pi * 256;
                int qq = p >> 5, kk = p & 31, r = (p >> 1) & 3;
                const float* zp = z + ((size_t)(q0 + qq) * NN + (size_t)(k0 + kk)) * CZ;
                #pragma unroll
                for (int gg = 0; gg < 4; gg++) {
                    int slot = (gg + r) & 3;
                    cpa16(&z_sh[p * 16 + slot * 4], zp + gg * 4);
                }
            }
            #pragma unroll
            for (int i = 0; i < 4; i++) {
                int cch = tid + i * 256;
                int row = cch >> 5, c4 = cch & 31;
                cpa16(&k_sh[buf * TK * KSTR + row * KSTR + c4 * 4],
                      &g_k[(size_t)(k0 + row) * CA + c4 * 4]);
                cpa16(&v_sh[buf * TK * KSTR + row * KSTR + c4 * 4],
                      &g_v[(size_t)(k0 + row) * CA + c4 * 4]);
            }
        }
        CPA_COMMIT();

        const float* kbuf = k_sh + (t & 1) * TK * KSTR;
        const float* vbuf = v_sh + (t & 1) * TK * KSTR;

        // ---- QK^T mma, C initialized with pair bias ----
        float c[4][4];
        #pragma unroll
        for (int kb = 0; kb < 4; kb++) {
            float2 b01 = *(const float2*)&b_sh[(rowg * NH + h) * PSTR + kb * 8 + 2 * t4];
            float2 b23 = *(const float2*)&b_sh[((rowg + 8) * NH + h) * PSTR + kb * 8 + 2 * t4];
            c[kb][0] = b01.x; c[kb][1] = b01.y;
            c[kb][2] = b23.x; c[kb][3] = b23.y;
        }
        #pragma unroll
        for (int dc = 0; dc < 4; dc++) {
            #pragma unroll
            for (int kb = 0; kb < 4; kb++) {
                const float* kp = &kbuf[(kb * 8 + g) * KSTR + h * DH + dc * 8 + t4];
                uint32_t b0 = tf32c(kp[0]);
                uint32_t b1 = tf32c(kp[4]);
                mma16n8k8(c[kb], qa + dc * 4, b0, b1);
            }
        }

        // ---- online softmax (rows rowg and rowg+8) ----
        float v0[8] = {c[0][0], c[0][1], c[1][0], c[1][1], c[2][0], c[2][1], c[3][0], c[3][1]};
        float v1[8] = {c[0][2], c[0][3], c[1][2], c[1][3], c[2][2], c[2][3], c[3][2], c[3][3]};
        float mx0 = v0[0], mx1 = v1[0];
        #pragma unroll
        for (int i = 1; i < 8; i++) { mx0 = fmaxf(mx0, v0[i]); mx1 = fmaxf(mx1, v1[i]); }
        mx0 = fmaxf(mx0, __shfl_xor_sync(0xffffffffu, mx0, 1));
        mx0 = fmaxf(mx0, __shfl_xor_sync(0xffffffffu, mx0, 2));
        mx1 = fmaxf(mx1, __shfl_xor_sync(0xffffffffu, mx1, 1));
        mx1 = fmaxf(mx1, __shfl_xor_sync(0xffffffffu, mx1, 2));
        float mn0 = fmaxf(m0, mx0), mn1 = fmaxf(m1, mx1);
        float sum0 = 0.f, sum1 = 0.f;
        #pragma unroll
        for (int i = 0; i < 8; i++) {
            v0[i] = __expf(v0[i] - mn0); sum0 += v0[i];
            v1[i] = __expf(v1[i] - mn1); sum1 += v1[i];
        }
        sum0 += __shfl_xor_sync(0xffffffffu, sum0, 1);
        sum0 += __shfl_xor_sync(0xffffffffu, sum0, 2);
        sum1 += __shfl_xor_sync(0xffffffffu, sum1, 1);
        sum1 += __shfl_xor_sync(0xffffffffu, sum1, 2);
        float scl0 = __expf(m0 - mn0), scl1 = __expf(m1 - mn1);
        l0 = l0 * scl0 + sum0; m0 = mn0;
        l1 = l1 * scl1 + sum1; m1 = mn1;

        // ---- store P to per-warp smem (C layout -> row-major) ----
        #pragma unroll
        for (int kb = 0; kb < 4; kb++) {
            *(float2*)&pw[g * PSTR + kb * 8 + 2 * t4]       = make_float2(v0[2 * kb], v0[2 * kb + 1]);
            *(float2*)&pw[(g + 8) * PSTR + kb * 8 + 2 * t4] = make_float2(v1[2 * kb], v1[2 * kb + 1]);
        }
        __syncwarp();

        // ---- rescale O ----
        #pragma unroll
        for (int nb = 0; nb < 4; nb++) {
            o[nb][0] *= scl0; o[nb][1] *= scl0;
            o[nb][2] *= scl1; o[nb][3] *= scl1;
        }

        // ---- P @ V mma ----
        #pragma unroll
        for (int kc = 0; kc < 4; kc++) {
            uint32_t pa[4];
            pa[0] = tf32c(pw[g * PSTR + kc * 8 + t4]);
            pa[1] = tf32c(pw[(g + 8) * PSTR + kc * 8 + t4]);
            pa[2] = tf32c(pw[g * PSTR + kc * 8 + t4 + 4]);
            pa[3] = tf32c(pw[(g + 8) * PSTR + kc * 8 + t4 + 4]);
            #pragma unroll
            for (int nb = 0; nb < 4; nb++) {
                const float* vp = &vbuf[(kc * 8 + t4) * KSTR + h * DH + nb * 8 + g];
                uint32_t b0 = tf32c(vp[0]);
                uint32_t b1 = tf32c(vp[4 * KSTR]);
                mma16n8k8(o[nb], pa, b0, b1);
            }
        }
        __syncwarp();   // pw fully consumed before next tile's stores
    }

    // ---- epilogue: normalize and write partials ----
    size_t sp = blockIdx.y;
    float il0 = 1.f / l0, il1 = 1.f / l1;
    #pragma unroll
    for (int nb = 0; nb < 4; nb++) {
        int q_a = q0 + rowg, q_b = q0 + rowg + 8;
        *(float2*)&g_po[(sp * NN + q_a) * CA + h * DH + nb * 8 + 2 * t4] =
            make_float2(o[nb][0] * il0, o[nb][1] * il0);
        *(float2*)&g_po[(sp * NN + q_b) * CA + h * DH + nb * 8 + 2 * t4] =
            make_float2(o[nb][2] * il1, o[nb][3] * il1);
    }
    if (t4 == 0) {
        int q_a = q0 + rowg, q_b = q0 + rowg + 8;
        g_pm[(sp * NN + q_a) * NH + h] = m0;
        g_pl[(sp * NN + q_a) * NH + h] = l0;
        g_pm[(sp * NN + q_b) * NH + h] = m1;
        g_pl[(sp * NN + q_b) * NH + h] = l1;
    }
}

// ---------------- split-K combine ----------------
__global__ void combine_kernel() {
    int tid = threadIdx.x;               // 256
    int q = blockIdx.x * 2 + (tid >> 7);
    int hd = tid & 127;
    int h = hd >> 5;
    float ms[NSPLIT];
    float M = -1e30f;
    #pragma unroll
    for (int s = 0; s < NSPLIT; s++) {
        ms[s] = g_pm[((size_t)s * NN + q) * NH + h];
        M = fmaxf(M, ms[s]);
    }
    float osum = 0.f, lsum = 0.f;
    #pragma unroll
    for (int s = 0; s < NSPLIT; s++) {
        float w = __expf(ms[s] - M);
        float lw = g_pl[((size_t)s * NN + q) * NH + h];
        lsum = fmaf(w, lw, lsum);
        osum = fmaf(w * lw, g_po[((size_t)s * NN + q) * CA + hd], osum);
    }
    g_o[(size_t)q * CA + hd] = osum / lsum;
}

// ---------------- output proj + style gate + residual 1, 16 rows/block ----------------
__global__ void attnout_kernel(const float* __restrict__ wo,
                               const float* __restrict__ s,
                               const float* __restrict__ sg1w,
                               const float* __restrict__ sg1b,
                               const float* __restrict__ a) {
    __shared__ float go_sh[16 * CA];
    __shared__ float s_sh[16 * CS];
    int r0 = blockIdx.x * 16;
    int tid = threadIdx.x;   // 512
    int cp = tid & 63;
    int rg = tid >> 6;       // 0..7
    for (int i = tid; i < 16 * CA; i += 512)
        go_sh[i] = g_g[(size_t)r0 * CA + i] * g_o[(size_t)r0 * CA + i];
    for (int i = tid; i < 16 * CS; i += 512)
        s_sh[i] = s[(size_t)r0 * CS + i];
    __syncthreads();
    const u64* wo2 = (const u64*)wo;
    const u64* sg2 = (const u64*)sg1w;
    u64 aA[2] = {0, 0};
    #pragma unroll 8
    for (int j = 0; j < CA; j++) {
        u64 w = wo2[j * 64 + cp];
        float g0 = go_sh[(2 * rg + 0) * CA + j];
        float g1 = go_sh[(2 * rg + 1) * CA + j];
        aA[0] = f2fma(pk2(g0, g0), w, aA[0]);
        aA[1] = f2fma(pk2(g1, g1), w, aA[1]);
    }
    u64 aG[2] = {0, 0};
    #pragma unroll 4
    for (int j = 0; j < CS; j++) {
        u64 w = sg2[j * 64 + cp];
        float s0 = s_sh[(2 * rg + 0) * CS + j];
        float s1 = s_sh[(2 * rg + 1) * CS + j];
        aG[0] = f2fma(pk2(s0, s0), w, aG[0]);
        aG[1] = f2fma(pk2(s1, s1), w, aG[1]);
    }
    float gb0 = sg1b[2 * cp], gb1 = sg1b[2 * cp + 1];
    #pragma unroll
    for (int rr = 0; rr < 2; rr++) {
        int row = r0 + 2 * rg + rr;
        float x0, x1, y0, y1;
        upk2(aA[rr], x0, x1);
        upk2(aG[rr], y0, y1);
        float2 av = ((const float2*)a)[(size_t)row * 64 + cp];
        float2 o;
        o.x = sigmoidf_(y0 + gb0) * x0 + av.x;
        o.y = sigmoidf_(y1 + gb1) * x1 + av.y;
        ((float2*)g_r1)[(size_t)row * 64 + cp] = o;
    }
}

// ---------------- SwiGLU FFN + gate + residual 2, 16 rows/block, 512 threads ----------------
__global__ void ffn_kernel(const float* __restrict__ w1, const float* __restrict__ w2,
                           const float* __restrict__ wout,
                           const float* __restrict__ s,
                           const float* __restrict__ sg2w, const float* __restrict__ sg2b,
                           float* __restrict__ out) {
    __shared__ float h_sh[16 * CA];
    __shared__ float s_sh[16 * CS];
    __shared__ __align__(16) float gt_sh[16 * CF];
    int r0 = blockIdx.x * 16;
    int tid = threadIdx.x;   // 512
    for (int i = tid; i < 16 * CA; i += 512) h_sh[i] = g_h2[(size_t)r0 * CA + i];
    for (int i = tid; i < 16 * CS; i += 512) s_sh[i] = s[(size_t)r0 * CS + i];
    __syncthreads();
    {
        int cpf = tid & 127;   // CF channel pair
        int rgf = tid >> 7;    // 0..3 -> rows rgf*4 .. rgf*4+3
        const u64* w1p = (const u64*)w1;
        const u64* w2p = (const u64*)w2;
        u64 u1[4] = {0, 0, 0, 0}, u2[4] = {0, 0, 0, 0};
        #pragma unroll 4
        for (int j = 0; j < CA; j++) {
            u64 wa = w1p[j * 128 + cpf];
            u64 wbv = w2p[j * 128 + cpf];
            #pragma unroll
            for (int rr = 0; rr < 4; rr++) {
                float hv = h_sh[(rgf * 4 + rr) * CA + j];
                u64 sv = pk2(hv, hv);
                u1[rr] = f2fma(sv, wa, u1[rr]);
                u2[rr] = f2fma(sv, wbv, u2[rr]);
            }
        }
        #pragma unroll
        for (int rr = 0; rr < 4; rr++) {
            float x0, x1, y0, y1;
            upk2(u1[rr], x0, x1);
            upk2(u2[rr], y0, y1);
            float g0 = (x0 * sigmoidf_(x0)) * y0;
            float g1 = (x1 * sigmoidf_(x1)) * y1;
            ((u64*)gt_sh)[(rgf * 4 + rr) * 128 + cpf] = pk2(g0, g1);
        }
    }
    __syncthreads();
    {
        int cp = tid & 63;
        int rw = tid >> 6;     // 0..7 -> rows 2rw, 2rw+1
        const u64* wop = (const u64*)wout;
        const u64* sgp = (const u64*)sg2w;
        u64 aF[2] = {0, 0}, aG[2] = {0, 0};
        #pragma unroll 8
        for (int j = 0; j < CF; j++) {
            u64 w = wop[j * 64 + cp];
            float g0 = gt_sh[(2 * rw + 0) * CF + j];
            float g1 = gt_sh[(2 * rw + 1) * CF + j];
            aF[0] = f2fma(pk2(g0, g0), w, aF[0]);
            aF[1] = f2fma(pk2(g1, g1), w, aF[1]);
        }
        #pragma unroll 4
        for (int j = 0; j < CS; j++) {
            u64 w = sgp[j * 64 + cp];
            float s0 = s_sh[(2 * rw + 0) * CS + j];
            float s1 = s_sh[(2 * rw + 1) * CS + j];
            aG[0] = f2fma(pk2(s0, s0), w, aG[0]);
            aG[1] = f2fma(pk2(s1, s1), w, aG[1]);
        }
        float gb0 = sg2b[2 * cp], gb1 = sg2b[2 * cp + 1];
        #pragma unroll
        for (int rr = 0; rr < 2; rr++) {
            int row = r0 + 2 * rw + rr;
            float f0, f1, gg0, gg1;
            upk2(aF[rr], f0, f1);
            upk2(aG[rr], gg0, gg1);
            float2 rv = ((const float2*)g_r1)[(size_t)row * 64 + cp];
            float2 o;
            o.x = sigmoidf_(gg0 + gb0) * f0 + rv.x;
            o.y = sigmoidf_(gg1 + gb1) * f1 + rv.y;
            ((float2*)out)[(size_t)row * 64 + cp] = o;
        }
    }
}

// ---------------- launch ----------------
extern "C" void kernel_launch(void* const* d_in, const int* in_sizes, int n_in,
                              void* d_out, int out_size) {
    const float* a      = (const float*)d_in[0];
    const float* s      = (const float*)d_in[1];
    const float* z      = (const float*)d_in[2];
    const float* a1sw   = (const float*)d_in[3];
    const float* a1scw  = (const float*)d_in[4];
    const float* a1scb  = (const float*)d_in[5];
    const float* a1shw  = (const float*)d_in[6];
    const float* wq     = (const float*)d_in[7];
    const float* bq     = (const float*)d_in[8];
    const float* wk     = (const float*)d_in[9];
    const float* wv     = (const float*)d_in[10];
    const float* lnzw   = (const float*)d_in[11];
    const float* lnzb   = (const float*)d_in[12];
    const float* wb     = (const float*)d_in[13];
    const float* wg     = (const float*)d_in[14];
    const float* wo     = (const float*)d_in[15];
    const float* sg1w   = (const float*)d_in[16];
    const float* sg1b   = (const float*)d_in[17];
    const float* a2sw   = (const float*)d_in[18];
    const float* a2scw  = (const float*)d_in[19];
    const float* a2scb  = (const float*)d_in[20];
    const float* a2shw  = (const float*)d_in[21];
    const float* w1     = (const float*)d_in[22];
    const float* w2     = (const float*)d_in[23];
    const float* wout   = (const float*)d_in[24];
    const float* sg2w   = (const float*)d_in[25];
    const float* sg2b   = (const float*)d_in[26];
    float* out = (float*)d_out;

    const int ATTN_SMEM =
        (TQ * KSTR + 4 * TK * KSTR + TQ * TK * 16 + 2 * TQ * NH * PSTR) * 4;
    static int attrset = 0;
    if (!attrset) {
        cudaFuncSetAttribute(attn_kernel, cudaFuncAttributeMaxDynamicSharedMemorySize, ATTN_SMEM);
        attrset = 1;
    }

    ln_kernel<CA><<<NN, 128>>>(a, g_an);
    ln_kernel<CS><<<NN, 128>>>(s, g_sn);
    adaln_kernel<<<NN / 16, 512>>>(g_an, a1sw, a1scw, a1shw, a1scb, g_h);
    qkvg_kernel<<<dim3(NN / 16, 2), 512>>>(wq, bq, wk, wv, wg);
    attn_kernel<<<dim3(NN / TQ, NSPLIT), ATHREADS, ATTN_SMEM>>>(z, lnzw, lnzb, wb);
    combine_kernel<<<NN / 2, 256>>>();
    attnout_kernel<<<NN / 16, 512>>>(wo, s, sg1w, sg1b, a);
    ln_kernel<CA><<<NN, 128>>>(g_r1, g_an2);
    adaln_kernel<<<NN / 16, 512>>>(g_an2, a2sw, a2scw, a2shw, a2scb, g_h2);
    ffn_kernel<<<NN / 16, 512>>>(w1, w2, wout, s, sg2w, sg2b, out);
    (void)in_sizes; (void)n_in; (void)out_size;
}

// round 5
// speedup vs baseline: 1.3012x; 1.1078x over previous
#include <cuda_runtime.h>
#include <cuda_fp16.h>
#include <math.h>
#include <stdint.h>

typedef unsigned long long u64;

#define NN 3072
#define CA 128
#define CS 384
#define CZ 16
#define NH 4
#define DH 32
#define CF 256
#define LNEPS 1e-5f

#define TQ 32
#define TK 32
#define NSPLIT 8
#define KPS (NN / NSPLIT)
#define NT (KPS / TK)
#define KSTR 132
#define PSTR 36
#define BSTR 40           // halves per bias row in smem
#define ATHREADS 256

// ---------------- scratch ----------------
static __device__ float g_an[NN*CA];
static __device__ float g_sn[NN*CS];
static __device__ float g_h[NN*CA];
static __device__ float g_q[NN*CA];
static __device__ float g_k[NN*CA];
static __device__ float g_v[NN*CA];
static __device__ float g_g[NN*CA];
static __device__ float g_o[NN*CA];
static __device__ float g_r1[NN*CA];
static __device__ float g_an2[NN*CA];
static __device__ float g_h2[NN*CA];
static __device__ float g_po[(size_t)NSPLIT*NN*CA];
static __device__ float g_pm[NSPLIT*NN*NH];
static __device__ float g_pl[NSPLIT*NN*NH];
static __device__ __half g_bias[(size_t)NH*NN*NN];   // 75.5 MB
static __device__ float g_u[NH*CZ];
static __device__ float g_su[NH];
static __device__ float g_cbp[NH];

__device__ __forceinline__ float sigmoidf_(float x) { return 1.f / (1.f + __expf(-x)); }

// ---------------- packed f32x2 helpers ----------------
__device__ __forceinline__ u64 pk2(float lo, float hi) {
    u64 r; asm("mov.b64 %0, {%1, %2};" : "=l"(r) : "f"(lo), "f"(hi)); return r;
}
__device__ __forceinline__ void upk2(u64 v, float& lo, float& hi) {
    asm("mov.b64 {%0, %1}, %2;" : "=f"(lo), "=f"(hi) : "l"(v));
}
__device__ __forceinline__ u64 f2fma(u64 a, u64 b, u64 c) {
    u64 d; asm("fma.rn.f32x2 %0, %1, %2, %3;" : "=l"(d) : "l"(a), "l"(b), "l"(c)); return d;
}

// ---------------- tf32 mma helpers ----------------
__device__ __forceinline__ uint32_t tf32c(float x) {
    uint32_t r; asm("cvt.rna.tf32.f32 %0, %1;" : "=r"(r) : "f"(x)); return r;
}
__device__ __forceinline__ void mma16n8k8(float* c, const uint32_t* a, uint32_t b0, uint32_t b1) {
    asm volatile(
        "mma.sync.aligned.m16n8k8.row.col.f32.tf32.tf32.f32 "
        "{%0,%1,%2,%3}, {%4,%5,%6,%7}, {%8,%9}, {%0,%1,%2,%3};"
        : "+f"(c[0]), "+f"(c[1]), "+f"(c[2]), "+f"(c[3])
        : "r"(a[0]), "r"(a[1]), "r"(a[2]), "r"(a[3]), "r"(b0), "r"(b1));
}

__device__ __forceinline__ void cpa16(void* dst_smem, const void* src) {
    uint32_t d = (uint32_t)__cvta_generic_to_shared(dst_smem);
    asm volatile("cp.async.ca.shared.global [%0], [%1], 16;\n" :: "r"(d), "l"(src));
}
#define CPA_COMMIT() asm volatile("cp.async.commit_group;\n" ::: "memory")
#define CPA_WAIT0()  asm volatile("cp.async.wait_group 0;\n" ::: "memory")

// ---------------- prep: fold LN(z)@wb constants ----------------
__global__ void prep_kernel(const float* __restrict__ lnzw,
                            const float* __restrict__ lnzb,
                            const float* __restrict__ wb) {
    int tid = threadIdx.x;  // 64
    if (tid < NH * CZ) {
        int h = tid >> 4, j = tid & 15;
        g_u[h * CZ + j] = lnzw[j] * wb[j * NH + h];
    }
    if (tid < NH) {
        float acc = 0.f;
        for (int j = 0; j < CZ; j++) acc += lnzw[j] * wb[j * NH + tid];
        g_su[tid] = acc;
    } else if (tid < 2 * NH) {
        int h = tid - NH;
        float acc = 0.f;
        for (int j = 0; j < CZ; j++) acc += lnzb[j] * wb[j * NH + h];
        g_cbp[h] = acc;
    }
}

// ---------------- bias kernel: streaming LN(z)@wb -> fp16 [h][q][k] ----------------
__global__ void __launch_bounds__(256)
bias_kernel(const float* __restrict__ z) {
    __shared__ float u_sh[NH * CZ], su_sh[NH], cbp_sh[NH];
    int tid = threadIdx.x;
    if (tid < NH * CZ) u_sh[tid] = g_u[tid];
    if (tid < NH) su_sh[tid] = g_su[tid];
    else if (tid < 2 * NH) cbp_sh[tid - NH] = g_cbp[tid - NH];
    __syncthreads();

    int q = blockIdx.x * 8 + (tid >> 5);
    int k = blockIdx.y * 32 + (tid & 31);
    const float* zp = z + ((size_t)q * NN + k) * CZ;
    float zv[16];
    *(float4*)&zv[0]  = *(const float4*)&zp[0];
    *(float4*)&zv[4]  = *(const float4*)&zp[4];
    *(float4*)&zv[8]  = *(const float4*)&zp[8];
    *(float4*)&zv[12] = *(const float4*)&zp[12];
    float sum = 0.f, zz = 0.f;
    #pragma unroll
    for (int j = 0; j < 16; j++) { sum += zv[j]; zz = fmaf(zv[j], zv[j], zz); }
    float mean = sum * (1.f / 16.f);
    float var = fmaf(-mean, mean, zz * (1.f / 16.f));
    float rs = rsqrtf(var + LNEPS);
    float rm = rs * mean;
    #pragma unroll
    for (int h = 0; h < NH; h++) {
        float d = 0.f;
        #pragma unroll
        for (int j = 0; j < 16; j++) d = fmaf(zv[j], u_sh[h * CZ + j], d);
        float b = fmaf(rs, d, fmaf(-rm, su_sh[h], cbp_sh[h]));
        g_bias[((size_t)h * NN + q) * NN + k] = __float2half(b);
    }
}

// ---------------- LN (no affine) ----------------
__device__ __forceinline__ float blockReduceSum128(float v, float* sh) {
    #pragma unroll
    for (int o = 16; o > 0; o >>= 1) v += __shfl_xor_sync(0xffffffffu, v, o);
    __syncthreads();
    if ((threadIdx.x & 31) == 0) sh[threadIdx.x >> 5] = v;
    __syncthreads();
    return sh[0] + sh[1] + sh[2] + sh[3];
}

template <int C>
__global__ void ln_kernel(const float* __restrict__ in, float* __restrict__ out) {
    __shared__ float sh[4];
    constexpr int PT = C / 128;
    int r = blockIdx.x;
    const float* row = in + (size_t)r * C;
    float v[PT];
    float lsum = 0.f;
    #pragma unroll
    for (int i = 0; i < PT; i++) { v[i] = row[threadIdx.x + i * 128]; lsum += v[i]; }
    float mean = blockReduceSum128(lsum, sh) * (1.f / (float)C);
    float lss = 0.f;
    #pragma unroll
    for (int i = 0; i < PT; i++) { float d = v[i] - mean; lss += d * d; }
    float var = blockReduceSum128(lss, sh) * (1.f / (float)C);
    float rs = rsqrtf(var + LNEPS);
    #pragma unroll
    for (int i = 0; i < PT; i++)
        out[(size_t)r * C + threadIdx.x + i * 128] = (v[i] - mean) * rs;
}

// ---------------- AdaLN, 4 rows/block, 128 threads ----------------
__global__ void adaln_kernel(const float* __restrict__ an_arr,
                             const float* __restrict__ s_w,
                             const float* __restrict__ scale_w,
                             const float* __restrict__ shift_w,
                             const float* __restrict__ scale_b,
                             float* __restrict__ out) {
    __shared__ float sn_sh[4 * CS];
    int r0 = blockIdx.x * 4;
    int tid = threadIdx.x;
    int cp = tid & 63;
    int rg = tid >> 6;
    #pragma unroll
    for (int i = 0; i < 4 * CS / 128; i++) {
        int idx = tid + i * 128;
        sn_sh[idx] = g_sn[(size_t)r0 * CS + idx] * s_w[idx % CS];
    }
    __syncthreads();
    const u64* sw2 = (const u64*)scale_w;
    const u64* hw2 = (const u64*)shift_w;
    u64 a1[2] = {0, 0}, a2[2] = {0, 0};
    #pragma unroll 4
    for (int j = 0; j < CS; j++) {
        u64 w1 = sw2[j * 64 + cp];
        u64 w2 = hw2[j * 64 + cp];
        float sv0 = sn_sh[(2 * rg + 0) * CS + j];
        float sv1 = sn_sh[(2 * rg + 1) * CS + j];
        u64 s0 = pk2(sv0, sv0), s1 = pk2(sv1, sv1);
        a1[0] = f2fma(s0, w1, a1[0]);
        a1[1] = f2fma(s1, w1, a1[1]);
        a2[0] = f2fma(s0, w2, a2[0]);
        a2[1] = f2fma(s1, w2, a2[1]);
    }
    float sb0 = scale_b[2 * cp], sb1 = scale_b[2 * cp + 1];
    #pragma unroll
    for (int rr = 0; rr < 2; rr++) {
        int row = r0 + 2 * rg + rr;
        float x0, x1, y0, y1;
        upk2(a1[rr], x0, x1);
        upk2(a2[rr], y0, y1);
        float2 anv = ((const float2*)an_arr)[(size_t)row * 64 + cp];
        float2 o;
        o.x = sigmoidf_(x0 + sb0) * anv.x + y0;
        o.y = sigmoidf_(x1 + sb1) * anv.y + y1;
        ((float2*)out)[(size_t)row * 64 + cp] = o;
    }
}

// ---------------- QKVG, 4 rows/block ----------------
__global__ void qkvg_kernel(const float* __restrict__ wq, const float* __restrict__ bq,
                            const float* __restrict__ wk, const float* __restrict__ wv,
                            const float* __restrict__ wg) {
    __shared__ float h_sh[4 * CA];
    int r0 = blockIdx.x * 4;
    int tid = threadIdx.x;
    int cp = tid & 63;
    int rg = tid >> 6;
    #pragma unroll
    for (int i = 0; i < 4; i++) {
        int idx = tid + i * 128;
        h_sh[idx] = g_h[(size_t)r0 * CA + idx];
    }
    __syncthreads();
    const u64* wA2 = (const u64*)((blockIdx.y == 0) ? wq : wk);
    const u64* wB2 = (const u64*)((blockIdx.y == 0) ? wg : wv);
    u64 aA[2] = {0, 0}, aB[2] = {0, 0};
    #pragma unroll 8
    for (int j = 0; j < CA; j++) {
        u64 w1 = wA2[j * 64 + cp];
        u64 w2 = wB2[j * 64 + cp];
        float h0 = h_sh[(2 * rg + 0) * CA + j];
        float h1 = h_sh[(2 * rg + 1) * CA + j];
        u64 s0 = pk2(h0, h0), s1 = pk2(h1, h1);
        aA[0] = f2fma(s0, w1, aA[0]);
        aA[1] = f2fma(s1, w1, aA[1]);
        aB[0] = f2fma(s0, w2, aB[0]);
        aB[1] = f2fma(s1, w2, aB[1]);
    }
    if (blockIdx.y == 0) {
        const float qscale = 0.17677669529663687f;
        float b0 = bq[2 * cp], b1 = bq[2 * cp + 1];
        #pragma unroll
        for (int rr = 0; rr < 2; rr++) {
            int row = r0 + 2 * rg + rr;
            float x0, x1, y0, y1;
            upk2(aA[rr], x0, x1);
            upk2(aB[rr], y0, y1);
            float2 q; q.x = (x0 + b0) * qscale; q.y = (x1 + b1) * qscale;
            float2 g; g.x = sigmoidf_(y0); g.y = sigmoidf_(y1);
            ((float2*)g_q)[(size_t)row * 64 + cp] = q;
            ((float2*)g_g)[(size_t)row * 64 + cp] = g;
        }
    } else {
        #pragma unroll
        for (int rr = 0; rr < 2; rr++) {
            int row = r0 + 2 * rg + rr;
            float x0, x1, y0, y1;
            upk2(aA[rr], x0, x1);
            upk2(aB[rr], y0, y1);
            ((float2*)g_k)[(size_t)row * 64 + cp] = make_float2(x0, x1);
            ((float2*)g_v)[(size_t)row * 64 + cp] = make_float2(y0, y1);
        }
    }
}

// ---------------- Attention: split-K, precomputed bias, tf32 mma, 2 blocks/SM ----------------
__global__ void __launch_bounds__(ATHREADS, 2)
attn_kernel() {
    extern __shared__ float sm[];
    float* k_sh = sm;                              // 2 bufs * TK*KSTR
    float* v_sh = k_sh + 2 * TK * KSTR;            // 2 bufs * TK*KSTR
    __half* b_sh = (__half*)(v_sh + 2 * TK * KSTR); // 2 bufs * NH*32*BSTR halves
    float* p_sh = (float*)(b_sh + 2 * NH * 32 * BSTR); // 8 warps * 16 * PSTR (q overlay)

    int tid = threadIdx.x;
    int q0 = blockIdx.x * TQ;
    int kbase = blockIdx.y * KPS;

    // ---- tile-0 async loads ----
    {
        int k0 = kbase;
        #pragma unroll
        for (int i = 0; i < 4; i++) {
            int cch = tid + i * 256;
            int row = cch >> 5, c4 = cch & 31;
            cpa16(&k_sh[row * KSTR + c4 * 4], &g_k[(size_t)(k0 + row) * CA + c4 * 4]);
            cpa16(&v_sh[row * KSTR + c4 * 4], &g_v[(size_t)(k0 + row) * CA + c4 * 4]);
        }
        #pragma unroll
        for (int i = 0; i < 2; i++) {
            int chunk = tid + i * 256;     // 0..511
            int hq = chunk >> 2, c = chunk & 3;
            int hh = hq >> 5, qq = hq & 31;
            const __half* src = &g_bias[((size_t)hh * NN + (q0 + qq)) * NN + k0 + c * 8];
            cpa16(&b_sh[(hh * 32 + qq) * BSTR + c * 8], src);
        }
    }
    CPA_COMMIT();

    // ---- stage Q into overlay region (p_sh) with KSTR stride ----
    #pragma unroll
    for (int i = 0; i < 4; i++) {
        int cch = tid + i * 256;
        int row = cch >> 5, c4 = cch & 31;
        *(float4*)&p_sh[row * KSTR + c4 * 4] =
            *(const float4*)&g_q[(size_t)(q0 + row) * CA + c4 * 4];
    }
    __syncthreads();

    int warp = tid >> 5, lane = tid & 31;
    int h = warp & 3;
    int qg = warp >> 2;
    int g = lane >> 2;
    int t4 = lane & 3;
    int rowg = qg * 16 + g;

    // Q fragments (tile-invariant)
    uint32_t qa[16];
    #pragma unroll
    for (int dc = 0; dc < 4; dc++) {
        const float* qp = &p_sh[rowg * KSTR + h * DH + dc * 8 + t4];
        qa[dc * 4 + 0] = tf32c(qp[0]);
        qa[dc * 4 + 1] = tf32c(qp[8 * KSTR]);
        qa[dc * 4 + 2] = tf32c(qp[4]);
        qa[dc * 4 + 3] = tf32c(qp[8 * KSTR + 4]);
    }
    __syncthreads();   // everyone done with Q; overlay becomes p_sh

    float* pw = p_sh + warp * 16 * PSTR;

    float m0 = -1e30f, m1 = -1e30f, l0 = 0.f, l1 = 0.f;
    float o[4][4];
    #pragma unroll
    for (int nb = 0; nb < 4; nb++)
        #pragma unroll
        for (int i = 0; i < 4; i++) o[nb][i] = 0.f;

    for (int t = 0; t < NT; t++) {
        CPA_WAIT0();
        __syncthreads();

        // ---- prefetch tile t+1 into other buffers ----
        if (t + 1 < NT) {
            int k0 = kbase + (t + 1) * TK;
            int buf = (t + 1) & 1;
            #pragma unroll
            for (int i = 0; i < 4; i++) {
                int cch = tid + i * 256;
                int row = cch >> 5, c4 = cch & 31;
                cpa16(&k_sh[buf * TK * KSTR + row * KSTR + c4 * 4],
                      &g_k[(size_t)(k0 + row) * CA + c4 * 4]);
                cpa16(&v_sh[buf * TK * KSTR + row * KSTR + c4 * 4],
                      &g_v[(size_t)(k0 + row) * CA + c4 * 4]);
            }
            #pragma unroll
            for (int i = 0; i < 2; i++) {
                int chunk = tid + i * 256;
                int hq = chunk >> 2, c = chunk & 3;
                int hh = hq >> 5, qq = hq & 31;
                const __half* src = &g_bias[((size_t)hh * NN + (q0 + qq)) * NN + k0 + c * 8];
                cpa16(&b_sh[buf * NH * 32 * BSTR + (hh * 32 + qq) * BSTR + c * 8], src);
            }
        }
        CPA_COMMIT();

        const float* kbuf = k_sh + (t & 1) * TK * KSTR;
        const float* vbuf = v_sh + (t & 1) * TK * KSTR;
        const __half* bbuf = b_sh + (t & 1) * NH * 32 * BSTR;

        // ---- QK^T mma with bias-initialized C ----
        float c[4][4];
        #pragma unroll
        for (int kb = 0; kb < 4; kb++) {
            __half2 hb01 = *(const __half2*)&bbuf[(h * 32 + rowg) * BSTR + kb * 8 + 2 * t4];
            __half2 hb23 = *(const __half2*)&bbuf[(h * 32 + rowg + 8) * BSTR + kb * 8 + 2 * t4];
            float2 b01 = __half22float2(hb01);
            float2 b23 = __half22float2(hb23);
            c[kb][0] = b01.x; c[kb][1] = b01.y;
            c[kb][2] = b23.x; c[kb][3] = b23.y;
        }
        #pragma unroll
        for (int dc = 0; dc < 4; dc++) {
            #pragma unroll
            for (int kb = 0; kb < 4; kb++) {
                const float* kp = &kbuf[(kb * 8 + g) * KSTR + h * DH + dc * 8 + t4];
                uint32_t b0 = tf32c(kp[0]);
                uint32_t b1 = tf32c(kp[4]);
                mma16n8k8(c[kb], qa + dc * 4, b0, b1);
            }
        }

        // ---- online softmax ----
        float v0[8] = {c[0][0], c[0][1], c[1][0], c[1][1], c[2][0], c[2][1], c[3][0], c[3][1]};
        float v1[8] = {c[0][2], c[0][3], c[1][2], c[1][3], c[2][2], c[2][3], c[3][2], c[3][3]};
        float mx0 = v0[0], mx1 = v1[0];
        #pragma unroll
        for (int i = 1; i < 8; i++) { mx0 = fmaxf(mx0, v0[i]); mx1 = fmaxf(mx1, v1[i]); }
        mx0 = fmaxf(mx0, __shfl_xor_sync(0xffffffffu, mx0, 1));
        mx0 = fmaxf(mx0, __shfl_xor_sync(0xffffffffu, mx0, 2));
        mx1 = fmaxf(mx1, __shfl_xor_sync(0xffffffffu, mx1, 1));
        mx1 = fmaxf(mx1, __shfl_xor_sync(0xffffffffu, mx1, 2));
        float mn0 = fmaxf(m0, mx0), mn1 = fmaxf(m1, mx1);
        float sum0 = 0.f, sum1 = 0.f;
        #pragma unroll
        for (int i = 0; i < 8; i++) {
            v0[i] = __expf(v0[i] - mn0); sum0 += v0[i];
            v1[i] = __expf(v1[i] - mn1); sum1 += v1[i];
        }
        sum0 += __shfl_xor_sync(0xffffffffu, sum0, 1);
        sum0 += __shfl_xor_sync(0xffffffffu, sum0, 2);
        sum1 += __shfl_xor_sync(0xffffffffu, sum1, 1);
        sum1 += __shfl_xor_sync(0xffffffffu, sum1, 2);
        float scl0 = __expf(m0 - mn0), scl1 = __expf(m1 - mn1);
        l0 = l0 * scl0 + sum0; m0 = mn0;
        l1 = l1 * scl1 + sum1; m1 = mn1;

        // ---- store P ----
        #pragma unroll
        for (int kb = 0; kb < 4; kb++) {
            *(float2*)&pw[g * PSTR + kb * 8 + 2 * t4]       = make_float2(v0[2 * kb], v0[2 * kb + 1]);
            *(float2*)&pw[(g + 8) * PSTR + kb * 8 + 2 * t4] = make_float2(v1[2 * kb], v1[2 * kb + 1]);
        }
        __syncwarp();

        // ---- rescale O ----
        #pragma unroll
        for (int nb = 0; nb < 4; nb++) {
            o[nb][0] *= scl0; o[nb][1] *= scl0;
            o[nb][2] *= scl1; o[nb][3] *= scl1;
        }

        // ---- P @ V ----
        #pragma unroll
        for (int kc = 0; kc < 4; kc++) {
            uint32_t pa[4];
            pa[0] = tf32c(pw[g * PSTR + kc * 8 + t4]);
            pa[1] = tf32c(pw[(g + 8) * PSTR + kc * 8 + t4]);
            pa[2] = tf32c(pw[g * PSTR + kc * 8 + t4 + 4]);
            pa[3] = tf32c(pw[(g + 8) * PSTR + kc * 8 + t4 + 4]);
            #pragma unroll
            for (int nb = 0; nb < 4; nb++) {
                const float* vp = &vbuf[(kc * 8 + t4) * KSTR + h * DH + nb * 8 + g];
                uint32_t b0 = tf32c(vp[0]);
                uint32_t b1 = tf32c(vp[4 * KSTR]);
                mma16n8k8(o[nb], pa, b0, b1);
            }
        }
        __syncwarp();
    }

    // ---- epilogue ----
    size_t sp = blockIdx.y;
    float il0 = 1.f / l0, il1 = 1.f / l1;
    #pragma unroll
    for (int nb = 0; nb < 4; nb++) {
        int q_a = q0 + rowg, q_b = q0 + rowg + 8;
        *(float2*)&g_po[(sp * NN + q_a) * CA + h * DH + nb * 8 + 2 * t4] =
            make_float2(o[nb][0] * il0, o[nb][1] * il0);
        *(float2*)&g_po[(sp * NN + q_b) * CA + h * DH + nb * 8 + 2 * t4] =
            make_float2(o[nb][2] * il1, o[nb][3] * il1);
    }
    if (t4 == 0) {
        int q_a = q0 + rowg, q_b = q0 + rowg + 8;
        g_pm[(sp * NN + q_a) * NH + h] = m0;
        g_pl[(sp * NN + q_a) * NH + h] = l0;
        g_pm[(sp * NN + q_b) * NH + h] = m1;
        g_pl[(sp * NN + q_b) * NH + h] = l1;
    }
}

// ---------------- split-K combine ----------------
__global__ void combine_kernel() {
    int tid = threadIdx.x;               // 256
    int q = blockIdx.x * 2 + (tid >> 7);
    int hd = tid & 127;
    int h = hd >> 5;
    float ms[NSPLIT];
    float M = -1e30f;
    #pragma unroll
    for (int s = 0; s < NSPLIT; s++) {
        ms[s] = g_pm[((size_t)s * NN + q) * NH + h];
        M = fmaxf(M, ms[s]);
    }
    float osum = 0.f, lsum = 0.f;
    #pragma unroll
    for (int s = 0; s < NSPLIT; s++) {
        float w = __expf(ms[s] - M);
        float lw = g_pl[((size_t)s * NN + q) * NH + h];
        lsum = fmaf(w, lw, lsum);
        osum = fmaf(w * lw, g_po[((size_t)s * NN + q) * CA + hd], osum);
    }
    g_o[(size_t)q * CA + hd] = osum / lsum;
}

// ---------------- output proj + style gate + residual 1 ----------------
__global__ void attnout_kernel(const float* __restrict__ wo,
                               const float* __restrict__ s,
                               const float* __restrict__ sg1w,
                               const float* __restrict__ sg1b,
                               const float* __restrict__ a) {
    __shared__ float go_sh[4 * CA];
    __shared__ float s_sh[4 * CS];
    int r0 = blockIdx.x * 4;
    int tid = threadIdx.x;
    int cp = tid & 63;
    int rg = tid >> 6;
    #pragma unroll
    for (int i = 0; i < 4; i++) {
        int idx = tid + i * 128;
        go_sh[idx] = g_g[(size_t)r0 * CA + idx] * g_o[(size_t)r0 * CA + idx];
    }
    #pragma unroll
    for (int i = 0; i < 4 * CS / 128; i++) {
        int idx = tid + i * 128;
        s_sh[idx] = s[(size_t)r0 * CS + idx];
    }
    __syncthreads();
    const u64* wo2 = (const u64*)wo;
    const u64* sg2 = (const u64*)sg1w;
    u64 aA[2] = {0, 0};
    #pragma unroll 8
    for (int j = 0; j < CA; j++) {
        u64 w = wo2[j * 64 + cp];
        float g0 = go_sh[(2 * rg + 0) * CA + j];
        float g1 = go_sh[(2 * rg + 1) * CA + j];
        aA[0] = f2fma(pk2(g0, g0), w, aA[0]);
        aA[1] = f2fma(pk2(g1, g1), w, aA[1]);
    }
    u64 aG[2] = {0, 0};
    #pragma unroll 4
    for (int j = 0; j < CS; j++) {
        u64 w = sg2[j * 64 + cp];
        float s0 = s_sh[(2 * rg + 0) * CS + j];
        float s1 = s_sh[(2 * rg + 1) * CS + j];
        aG[0] = f2fma(pk2(s0, s0), w, aG[0]);
        aG[1] = f2fma(pk2(s1, s1), w, aG[1]);
    }
    float gb0 = sg1b[2 * cp], gb1 = sg1b[2 * cp + 1];
    #pragma unroll
    for (int rr = 0; rr < 2; rr++) {
        int row = r0 + 2 * rg + rr;
        float x0, x1, y0, y1;
        upk2(aA[rr], x0, x1);
        upk2(aG[rr], y0, y1);
        float2 av = ((const float2*)a)[(size_t)row * 64 + cp];
        float2 o;
        o.x = sigmoidf_(y0 + gb0) * x0 + av.x;
        o.y = sigmoidf_(y1 + gb1) * x1 + av.y;
        ((float2*)g_r1)[(size_t)row * 64 + cp] = o;
    }
}

// ---------------- SwiGLU FFN + gate + residual 2, 4 rows/block, 256 threads ----------------
__global__ void ffn_kernel(const float* __restrict__ w1, const float* __restrict__ w2,
                           const float* __restrict__ wout,
                           const float* __restrict__ s,
                           const float* __restrict__ sg2w, const float* __restrict__ sg2b,
                           float* __restrict__ out) {
    __shared__ float h_sh[4 * CA];
    __shared__ float s_sh[4 * CS];
    __shared__ __align__(16) float gt_sh[4 * CF];
    int r0 = blockIdx.x * 4;
    int tid = threadIdx.x;   // 256
    for (int i = tid; i < 4 * CA; i += 256) h_sh[i] = g_h2[(size_t)r0 * CA + i];
    for (int i = tid; i < 4 * CS; i += 256) s_sh[i] = s[(size_t)r0 * CS + i];
    __syncthreads();
    {
        int cp = tid & 127;
        int rg = tid >> 7;
        const u64* w1p = (const u64*)w1;
        const u64* w2p = (const u64*)w2;
        u64 u1[2] = {0, 0}, u2[2] = {0, 0};
        #pragma unroll 8
        for (int j = 0; j < CA; j++) {
            u64 wa = w1p[j * 128 + cp];
            u64 wbv = w2p[j * 128 + cp];
            float h0 = h_sh[(2 * rg + 0) * CA + j];
            float h1 = h_sh[(2 * rg + 1) * CA + j];
            u64 s0 = pk2(h0, h0), s1 = pk2(h1, h1);
            u1[0] = f2fma(s0, wa, u1[0]);
            u1[1] = f2fma(s1, wa, u1[1]);
            u2[0] = f2fma(s0, wbv, u2[0]);
            u2[1] = f2fma(s1, wbv, u2[1]);
        }
        #pragma unroll
        for (int rr = 0; rr < 2; rr++) {
            float x0, x1, y0, y1;
            upk2(u1[rr], x0, x1);
            upk2(u2[rr], y0, y1);
            float g0 = (x0 * sigmoidf_(x0)) * y0;
            float g1 = (x1 * sigmoidf_(x1)) * y1;
            ((u64*)gt_sh)[(2 * rg + rr) * 128 + cp] = pk2(g0, g1);
        }
    }
    __syncthreads();
    {
        int cp = tid & 63;
        int rw = tid >> 6;   // 0..3
        const u64* wop = (const u64*)wout;
        const u64* sgp = (const u64*)sg2w;
        u64 aF = 0, aG = 0;
        #pragma unroll 8
        for (int j = 0; j < CF; j++) {
            u64 w = wop[j * 64 + cp];
            float gv = gt_sh[rw * CF + j];
            aF = f2fma(pk2(gv, gv), w, aF);
        }
        #pragma unroll 4
        for (int j = 0; j < CS; j++) {
            u64 w = sgp[j * 64 + cp];
            float sv = s_sh[rw * CS + j];
            aG = f2fma(pk2(sv, sv), w, aG);
        }
        float f0, f1, g0, g1;
        upk2(aF, f0, f1);
        upk2(aG, g0, g1);
        int row = r0 + rw;
        float2 rv = ((const float2*)g_r1)[(size_t)row * 64 + cp];
        float2 o;
        o.x = sigmoidf_(g0 + sg2b[2 * cp]) * f0 + rv.x;
        o.y = sigmoidf_(g1 + sg2b[2 * cp + 1]) * f1 + rv.y;
        ((float2*)out)[(size_t)row * 64 + cp] = o;
    }
}

// ---------------- launch ----------------
extern "C" void kernel_launch(void* const* d_in, const int* in_sizes, int n_in,
                              void* d_out, int out_size) {
    const float* a      = (const float*)d_in[0];
    const float* s      = (const float*)d_in[1];
    const float* z      = (const float*)d_in[2];
    const float* a1sw   = (const float*)d_in[3];
    const float* a1scw  = (const float*)d_in[4];
    const float* a1scb  = (const float*)d_in[5];
    const float* a1shw  = (const float*)d_in[6];
    const float* wq     = (const float*)d_in[7];
    const float* bq     = (const float*)d_in[8];
    const float* wk     = (const float*)d_in[9];
    const float* wv     = (const float*)d_in[10];
    const float* lnzw   = (const float*)d_in[11];
    const float* lnzb   = (const float*)d_in[12];
    const float* wb     = (const float*)d_in[13];
    const float* wg     = (const float*)d_in[14];
    const float* wo     = (const float*)d_in[15];
    const float* sg1w   = (const float*)d_in[16];
    const float* sg1b   = (const float*)d_in[17];
    const float* a2sw   = (const float*)d_in[18];
    const float* a2scw  = (const float*)d_in[19];
    const float* a2scb  = (const float*)d_in[20];
    const float* a2shw  = (const float*)d_in[21];
    const float* w1     = (const float*)d_in[22];
    const float* w2     = (const float*)d_in[23];
    const float* wout   = (const float*)d_in[24];
    const float* sg2w   = (const float*)d_in[25];
    const float* sg2b   = (const float*)d_in[26];
    float* out = (float*)d_out;

    const int ATTN_SMEM = (2 * TK * KSTR * 2 + 8 * 16 * PSTR) * 4 + 2 * NH * 32 * BSTR * 2;
    static int attrset = 0;
    if (!attrset) {
        cudaFuncSetAttribute(attn_kernel, cudaFuncAttributeMaxDynamicSharedMemorySize, ATTN_SMEM);
        attrset = 1;
    }

    prep_kernel<<<1, 64>>>(lnzw, lnzb, wb);
    bias_kernel<<<dim3(NN / 8, NN / 32), 256>>>(z);
    ln_kernel<CA><<<NN, 128>>>(a, g_an);
    ln_kernel<CS><<<NN, 128>>>(s, g_sn);
    adaln_kernel<<<NN / 4, 128>>>(g_an, a1sw, a1scw, a1shw, a1scb, g_h);
    qkvg_kernel<<<dim3(NN / 4, 2), 128>>>(wq, bq, wk, wv, wg);
    attn_kernel<<<dim3(NN / TQ, NSPLIT), ATHREADS, ATTN_SMEM>>>();
    combine_kernel<<<NN / 2, 256>>>();
    attnout_kernel<<<NN / 4, 128>>>(wo, s, sg1w, sg1b, a);
    ln_kernel<CA><<<NN, 128>>>(g_r1, g_an2);
    adaln_kernel<<<NN / 4, 128>>>(g_an2, a2sw, a2scw, a2shw, a2scb, g_h2);
    ffn_kernel<<<NN / 4, 256>>>(w1, w2, wout, s, sg2w, sg2b, out);
    (void)in_sizes; (void)n_in; (void)out_size;
}